// round 12
// baseline (speedup 1.0000x reference)
#include <cuda_runtime.h>
#include <math.h>

#define NN 384
#define C 128
#define NH 4
#define DH 32
#define HD 128
#define RK 96
#define SD 449
#define ZD 577
#define MH 256
#define MROWS (NN * NN)

typedef unsigned long long ull;

// ---- scratch (device globals; no allocation) ----
__device__ float g_xln[MROWS * C];
__device__ float g_q[MROWS * HD];
__device__ float g_k[MROWS * HD];
__device__ float g_v[MROWS * HD];
__device__ float g_gt[MROWS * HD];
__device__ float g_o[MROWS * HD];
__device__ float g_mean[2 * NN * C];
__device__ float g_qb[NH * NN * RK];
__device__ float g_kb[NH * NN * RK];
__device__ float g_bias[NH * NN * NN];

// ---- f32x2 packed helpers (FFMA2 path, sm_103a) ----
__device__ __forceinline__ ull d2(float v) {
    ull r; asm("mov.b64 %0, {%1, %1};" : "=l"(r) : "f"(v)); return r;
}
__device__ __forceinline__ void fma2(ull& d, ull a, ull b) {
    asm("fma.rn.f32x2 %0, %1, %2, %0;" : "+l"(d) : "l"(a), "l"(b));
}
__device__ __forceinline__ ull add2(ull a, ull b) {
    ull r; asm("add.rn.f32x2 %0, %1, %2;" : "=l"(r) : "l"(a), "l"(b)); return r;
}
__device__ __forceinline__ ull mul2(ull a, ull b) {
    ull r; asm("mul.rn.f32x2 %0, %1, %2;" : "=l"(r) : "l"(a), "l"(b)); return r;
}
__device__ __forceinline__ float2 unpk(ull v) {
    float2 f; asm("mov.b64 {%0, %1}, %2;" : "=f"(f.x), "=f"(f.y) : "l"(v)); return f;
}

// ---------------- LayerNorm: one warp per 128-ch row ----------------
__global__ __launch_bounds__(256) void k_ln(const float* __restrict__ x,
                                            const float* __restrict__ gamma,
                                            const float* __restrict__ beta) {
    int row = blockIdx.x * 8 + (threadIdx.x >> 5);
    int lane = threadIdx.x & 31;
    float4 v = reinterpret_cast<const float4*>(x + (size_t)row * C)[lane];
    float s = v.x + v.y + v.z + v.w;
    float s2 = v.x * v.x + v.y * v.y + v.z * v.z + v.w * v.w;
#pragma unroll
    for (int o = 16; o; o >>= 1) {
        s += __shfl_xor_sync(0xffffffffu, s, o);
        s2 += __shfl_xor_sync(0xffffffffu, s2, o);
    }
    float mu = s * (1.0f / C);
    float var = fmaxf(s2 * (1.0f / C) - mu * mu, 0.0f);
    float rs = rsqrtf(var + 1e-5f);
    float4 g4 = reinterpret_cast<const float4*>(gamma)[lane];
    float4 b4 = reinterpret_cast<const float4*>(beta)[lane];
    float4 o4;
    o4.x = (v.x - mu) * rs * g4.x + b4.x;
    o4.y = (v.y - mu) * rs * g4.y + b4.y;
    o4.z = (v.z - mu) * rs * g4.z + b4.z;
    o4.w = (v.w - mu) * rs * g4.w + b4.w;
    reinterpret_cast<float4*>(g_xln + (size_t)row * C)[lane] = o4;
}

// ---------------- row/col means ----------------
__global__ __launch_bounds__(128) void k_mean() {
    int n = blockIdx.x, c = threadIdx.x;
    float s = 0.f;
    if (blockIdx.y == 0) {
        const float* p = g_xln + (size_t)n * NN * C + c;
#pragma unroll 4
        for (int j = 0; j < NN; ++j) s += p[(size_t)j * C];
    } else {
        const float* p = g_xln + (size_t)n * C + c;
#pragma unroll 4
        for (int i = 0; i < NN; ++i) s += p[(size_t)i * NN * C];
    }
    g_mean[blockIdx.y * NN * C + n * C + c] = s * (1.0f / NN);
}

// ---------------- bias MLPs, 8 sequence positions per block ----------------
__global__ __launch_bounds__(256) void k_mlp(const float* __restrict__ s_inputs,
                                             const float* __restrict__ Wq1, const float* __restrict__ Wq2,
                                             const float* __restrict__ Wq3, const float* __restrict__ Wk1,
                                             const float* __restrict__ Wk2, const float* __restrict__ Wk3) {
    __shared__ float z[8][ZD];
    __shared__ float h1[8][MH];
    __shared__ float h2[8][MH];
    int n0 = blockIdx.x * 8, t = threadIdx.x;
    int which = blockIdx.y;
    const float* mean = g_mean + which * NN * C;
    const float* W1 = which ? Wk1 : Wq1;
    const float* W2 = which ? Wk2 : Wq2;
    const float* W3 = which ? Wk3 : Wq3;
    float* outb = which ? g_kb : g_qb;

    for (int idx = t; idx < 8 * ZD; idx += 256) {
        int n = idx / ZD, c = idx - n * ZD;
        z[n][c] = (c < C) ? mean[(n0 + n) * C + c] : s_inputs[(n0 + n) * SD + (c - C)];
    }
    __syncthreads();
    {
        float a[8];
#pragma unroll
        for (int n = 0; n < 8; ++n) a[n] = 0.f;
        for (int k = 0; k < ZD; ++k) {
            float wv = W1[k * MH + t];
#pragma unroll
            for (int n = 0; n < 8; ++n) a[n] = fmaf(z[n][k], wv, a[n]);
        }
#pragma unroll
        for (int n = 0; n < 8; ++n) h1[n][t] = tanhf(a[n]);
    }
    __syncthreads();
    {
        float a[8];
#pragma unroll
        for (int n = 0; n < 8; ++n) a[n] = 0.f;
        for (int k = 0; k < MH; ++k) {
            float wv = W2[k * MH + t];
#pragma unroll
            for (int n = 0; n < 8; ++n) a[n] = fmaf(h1[n][k], wv, a[n]);
        }
#pragma unroll
        for (int n = 0; n < 8; ++n) h2[n][t] = tanhf(a[n]);
    }
    __syncthreads();
    for (int o = t; o < NH * RK; o += 256) {
        float b[8];
#pragma unroll
        for (int n = 0; n < 8; ++n) b[n] = 0.f;
        for (int k = 0; k < MH; ++k) {
            float wv = W3[k * (NH * RK) + o];
#pragma unroll
            for (int n = 0; n < 8; ++n) b[n] = fmaf(h2[n][k], wv, b[n]);
        }
        int hh = o / RK, r = o - hh * RK;
#pragma unroll
        for (int n = 0; n < 8; ++n) outb[(hh * NN + n0 + n) * RK + r] = b[n];
    }
}

// ---------------- low-rank bias matrix: tiled B[h] = qb @ kb^T ----------------
__global__ __launch_bounds__(256) void k_biasmat() {
    extern __shared__ float smb[];
    float* qs = smb;             // [64][97]
    float* ks = smb + 64 * 97;   // [64][97]
    int q0 = blockIdx.x * 64, k0 = blockIdx.y * 64, h = blockIdx.z;
    for (int idx = threadIdx.x; idx < 64 * RK; idx += 256) {
        int row = idx / RK, r = idx - row * RK;
        qs[row * 97 + r] = g_qb[(h * NN + q0 + row) * RK + r];
        ks[row * 97 + r] = g_kb[(h * NN + k0 + row) * RK + r];
    }
    __syncthreads();
    int tx = threadIdx.x & 15, ty = threadIdx.x >> 4;
    float acc[4][4];
#pragma unroll
    for (int i = 0; i < 4; ++i)
#pragma unroll
        for (int j = 0; j < 4; ++j) acc[i][j] = 0.f;
    for (int r = 0; r < RK; ++r) {
        float qv[4], kv[4];
#pragma unroll
        for (int i = 0; i < 4; ++i) qv[i] = qs[(ty * 4 + i) * 97 + r];
#pragma unroll
        for (int j = 0; j < 4; ++j) kv[j] = ks[(tx * 4 + j) * 97 + r];
#pragma unroll
        for (int i = 0; i < 4; ++i)
#pragma unroll
            for (int j = 0; j < 4; ++j) acc[i][j] = fmaf(qv[i], kv[j], acc[i][j]);
    }
#pragma unroll
    for (int i = 0; i < 4; ++i) {
        float4 o4 = {acc[i][0], acc[i][1], acc[i][2], acc[i][3]};
        *reinterpret_cast<float4*>(g_bias + ((size_t)(h * NN + q0 + ty * 4 + i)) * NN + k0 + tx * 4) = o4;
    }
}

// ---------------- fused QKVG projection GEMM (f32x2, 2 weights resident) ----------------
__global__ __launch_bounds__(256) void k_proj(const float* __restrict__ Wq, const float* __restrict__ Wk,
                                              const float* __restrict__ Wv, const float* __restrict__ Wg,
                                              const float* __restrict__ bg) {
    extern __shared__ float sm[];
    float* Xs = sm;                 // [64][128]
    float* Ws0 = sm + 64 * 128;     // [128][128]
    float* Ws1 = Ws0 + 128 * 128;   // [128][128]
    int row0 = blockIdx.x * 64;
    {
        const float4* src = reinterpret_cast<const float4*>(g_xln + (size_t)row0 * C);
        float4* d4 = reinterpret_cast<float4*>(Xs);
        for (int idx = threadIdx.x; idx < 64 * 128 / 4; idx += 256) d4[idx] = src[idx];
    }
    int tx = threadIdx.x & 31, ty = threadIdx.x >> 5;
    const float* WA[4] = {Wq, Wk, Wv, Wg};
    float* OA[4] = {g_q, g_k, g_v, g_gt};
    float4 bg4 = reinterpret_cast<const float4*>(bg)[tx];

#pragma unroll 1
    for (int pass = 0; pass < 2; ++pass) {
        __syncthreads();
        {
            const float4* s0 = reinterpret_cast<const float4*>(WA[2 * pass]);
            const float4* s1 = reinterpret_cast<const float4*>(WA[2 * pass + 1]);
            float4* d0 = reinterpret_cast<float4*>(Ws0);
            float4* d1 = reinterpret_cast<float4*>(Ws1);
            for (int idx = threadIdx.x; idx < 128 * 128 / 4; idx += 256) {
                d0[idx] = s0[idx];
                d1[idx] = s1[idx];
            }
        }
        __syncthreads();
        ull acc[8][2][2];
#pragma unroll
        for (int i = 0; i < 8; ++i)
#pragma unroll
            for (int w = 0; w < 2; ++w) { acc[i][w][0] = 0ull; acc[i][w][1] = 0ull; }

        for (int k0 = 0; k0 < 128; k0 += 4) {
            ulonglong2 w0[4], w1[4];
#pragma unroll
            for (int j = 0; j < 4; ++j) {
                w0[j] = reinterpret_cast<const ulonglong2*>(Ws0 + (k0 + j) * 128)[tx];
                w1[j] = reinterpret_cast<const ulonglong2*>(Ws1 + (k0 + j) * 128)[tx];
            }
#pragma unroll
            for (int i = 0; i < 8; ++i) {
                float4 xv = *reinterpret_cast<const float4*>(Xs + (ty + 8 * i) * 128 + k0);
                ull xd[4] = {d2(xv.x), d2(xv.y), d2(xv.z), d2(xv.w)};
#pragma unroll
                for (int j = 0; j < 4; ++j) {
                    fma2(acc[i][0][0], xd[j], w0[j].x);
                    fma2(acc[i][0][1], xd[j], w0[j].y);
                    fma2(acc[i][1][0], xd[j], w1[j].x);
                    fma2(acc[i][1][1], xd[j], w1[j].y);
                }
            }
        }
#pragma unroll
        for (int w = 0; w < 2; ++w) {
            int wi = 2 * pass + w;
            float* outp = OA[wi];
#pragma unroll
            for (int i = 0; i < 8; ++i) {
                float2 a = unpk(acc[i][w][0]), b = unpk(acc[i][w][1]);
                float vals[4] = {a.x, a.y, b.x, b.y};
                float bb[4] = {bg4.x, bg4.y, bg4.z, bg4.w};
#pragma unroll
                for (int c = 0; c < 4; ++c) {
                    if (wi == 0) vals[c] *= 0.17677669529663687f;  // 1/sqrt(32)
                    if (wi == 3) vals[c] = 1.0f / (1.0f + __expf(-(vals[c] + bb[c])));
                }
                float4 o4 = {vals[0], vals[1], vals[2], vals[3]};
                *reinterpret_cast<float4*>(outp + (size_t)(row0 + ty + 8 * i) * 128 + tx * 4) = o4;
            }
        }
    }
}

// ---------------- attention: block per (row i, head h), 2 q-rows per thread ----------------
__global__ __launch_bounds__(192, 1) void k_attn() {
    extern __shared__ float sm[];
    float* Ks = sm;              // [384][32]
    float* Vs = sm + NN * DH;    // [384][32]
    int i = blockIdx.x, h = blockIdx.y;
    int tid = threadIdx.x;
    size_t base = ((size_t)i * NN) * HD + h * DH;

    for (int idx = tid; idx < NN * DH / 4; idx += 192) {
        int k = idx >> 3, d4 = idx & 7;
        reinterpret_cast<float4*>(Ks)[idx] = *reinterpret_cast<const float4*>(g_k + base + (size_t)k * HD + d4 * 4);
        reinterpret_cast<float4*>(Vs)[idx] = *reinterpret_cast<const float4*>(g_v + base + (size_t)k * HD + d4 * 4);
    }
    __syncthreads();

    int qA = tid, qB = tid + 192;
    ull qa[16], qb[16];
    {
        const ulonglong2* pa = reinterpret_cast<const ulonglong2*>(g_q + base + (size_t)qA * HD);
        const ulonglong2* pb = reinterpret_cast<const ulonglong2*>(g_q + base + (size_t)qB * HD);
#pragma unroll
        for (int t = 0; t < 8; ++t) {
            ulonglong2 ua = pa[t], ub = pb[t];
            qa[2 * t] = ua.x; qa[2 * t + 1] = ua.y;
            qb[2 * t] = ub.x; qb[2 * t + 1] = ub.y;
        }
    }
    const float4* browA = reinterpret_cast<const float4*>(g_bias + ((size_t)(h * NN + qA)) * NN);
    const float4* browB = reinterpret_cast<const float4*>(g_bias + ((size_t)(h * NN + qB)) * NN);

    float ma = -INFINITY, la = 0.f, mb = -INFINITY, lb = 0.f;
    ull aa[16], ab[16];
#pragma unroll
    for (int t = 0; t < 16; ++t) { aa[t] = 0ull; ab[t] = 0ull; }

    float4 pba = browA[0], pbb = browB[0];

    for (int k0 = 0; k0 < NN; k0 += 4) {
        float4 b4a = pba, b4b = pbb;
        if (k0 + 4 < NN) { pba = browA[(k0 >> 2) + 1]; pbb = browB[(k0 >> 2) + 1]; }
        float sva[4] = {b4a.x, b4a.y, b4a.z, b4a.w};
        float svb[4] = {b4b.x, b4b.y, b4b.z, b4b.w};
#pragma unroll
        for (int j = 0; j < 4; ++j) {
            const ulonglong2* kp = reinterpret_cast<const ulonglong2*>(Ks + (k0 + j) * DH);
            ull sA0 = 0ull, sB0 = 0ull, sA1 = 0ull, sB1 = 0ull;
#pragma unroll
            for (int t = 0; t < 8; ++t) {
                ulonglong2 kk = kp[t];
                fma2(sA0, qa[2 * t], kk.x);
                fma2(sB0, qa[2 * t + 1], kk.y);
                fma2(sA1, qb[2 * t], kk.x);
                fma2(sB1, qb[2 * t + 1], kk.y);
            }
            float2 r0 = unpk(add2(sA0, sB0));
            float2 r1 = unpk(add2(sA1, sB1));
            sva[j] += r0.x + r0.y;
            svb[j] += r1.x + r1.y;
        }
        // online softmax for qA
        float mxa = fmaxf(fmaxf(sva[0], sva[1]), fmaxf(sva[2], sva[3]));
        if (mxa > ma) {
            float sc = __expf(ma - mxa);
            ull sc2 = d2(sc);
#pragma unroll
            for (int t = 0; t < 16; ++t) aa[t] = mul2(aa[t], sc2);
            la *= sc;
            ma = mxa;
        }
        float mxb = fmaxf(fmaxf(svb[0], svb[1]), fmaxf(svb[2], svb[3]));
        if (mxb > mb) {
            float sc = __expf(mb - mxb);
            ull sc2 = d2(sc);
#pragma unroll
            for (int t = 0; t < 16; ++t) ab[t] = mul2(ab[t], sc2);
            lb *= sc;
            mb = mxb;
        }
        float pa4[4], pb4[4];
#pragma unroll
        for (int j = 0; j < 4; ++j) {
            pa4[j] = __expf(sva[j] - ma);
            pb4[j] = __expf(svb[j] - mb);
        }
        la += pa4[0] + pa4[1] + pa4[2] + pa4[3];
        lb += pb4[0] + pb4[1] + pb4[2] + pb4[3];
#pragma unroll
        for (int j = 0; j < 4; ++j) {
            ull p2a = d2(pa4[j]);
            ull p2b = d2(pb4[j]);
            const ulonglong2* vp = reinterpret_cast<const ulonglong2*>(Vs + (k0 + j) * DH);
#pragma unroll
            for (int t = 0; t < 8; ++t) {
                ulonglong2 vv = vp[t];
                fma2(aa[2 * t], p2a, vv.x);
                fma2(aa[2 * t + 1], p2a, vv.y);
                fma2(ab[2 * t], p2b, vv.x);
                fma2(ab[2 * t + 1], p2b, vv.y);
            }
        }
    }
    float ia = 1.0f / la, ib = 1.0f / lb;
    float* opa = g_o + base + (size_t)qA * HD;
    float* opb = g_o + base + (size_t)qB * HD;
#pragma unroll
    for (int t = 0; t < 8; ++t) {
        float2 a0 = unpk(aa[2 * t]), a1 = unpk(aa[2 * t + 1]);
        float2 b0 = unpk(ab[2 * t]), b1 = unpk(ab[2 * t + 1]);
        float4 o4a = {a0.x * ia, a0.y * ia, a1.x * ia, a1.y * ia};
        float4 o4b = {b0.x * ib, b0.y * ib, b1.x * ib, b1.y * ib};
        *reinterpret_cast<float4*>(opa + t * 4) = o4a;
        *reinterpret_cast<float4*>(opb + t * 4) = o4b;
    }
}

// ---------------- output: (g*o) @ Wo + bo (f32x2) ----------------
__global__ __launch_bounds__(256) void k_out(const float* __restrict__ Wo, const float* __restrict__ bo,
                                             float* __restrict__ out) {
    extern __shared__ float sm[];
    float* Xs = sm;
    float* Ws = sm + 64 * 128;
    int row0 = blockIdx.x * 64;
    {
        const float4* sg = reinterpret_cast<const float4*>(g_gt + (size_t)row0 * 128);
        const float4* so = reinterpret_cast<const float4*>(g_o + (size_t)row0 * 128);
        float4* d4 = reinterpret_cast<float4*>(Xs);
        for (int idx = threadIdx.x; idx < 64 * 128 / 4; idx += 256) {
            float4 a = sg[idx], b = so[idx];
            d4[idx] = make_float4(a.x * b.x, a.y * b.y, a.z * b.z, a.w * b.w);
        }
        const float4* src = reinterpret_cast<const float4*>(Wo);
        float4* w4 = reinterpret_cast<float4*>(Ws);
        for (int idx = threadIdx.x; idx < 128 * 128 / 4; idx += 256) w4[idx] = src[idx];
    }
    __syncthreads();
    int tx = threadIdx.x & 31, ty = threadIdx.x >> 5;
    ull acc[8][2];
#pragma unroll
    for (int i = 0; i < 8; ++i) { acc[i][0] = 0ull; acc[i][1] = 0ull; }

    for (int k0 = 0; k0 < 128; k0 += 4) {
        ulonglong2 wv[4];
#pragma unroll
        for (int j = 0; j < 4; ++j)
            wv[j] = reinterpret_cast<const ulonglong2*>(Ws + (k0 + j) * 128)[tx];
#pragma unroll
        for (int i = 0; i < 8; ++i) {
            float4 xv = *reinterpret_cast<const float4*>(Xs + (ty + 8 * i) * 128 + k0);
            ull xd[4] = {d2(xv.x), d2(xv.y), d2(xv.z), d2(xv.w)};
#pragma unroll
            for (int j = 0; j < 4; ++j) {
                fma2(acc[i][0], xd[j], wv[j].x);
                fma2(acc[i][1], xd[j], wv[j].y);
            }
        }
    }
    float4 bo4 = reinterpret_cast<const float4*>(bo)[tx];
#pragma unroll
    for (int i = 0; i < 8; ++i) {
        float2 a = unpk(acc[i][0]), b = unpk(acc[i][1]);
        float4 o4 = {a.x + bo4.x, a.y + bo4.y, b.x + bo4.z, b.y + bo4.w};
        *reinterpret_cast<float4*>(out + (size_t)(row0 + ty + 8 * i) * 128 + tx * 4) = o4;
    }
}

extern "C" void kernel_launch(void* const* d_in, const int* in_sizes, int n_in,
                              void* d_out, int out_size) {
    const float* x        = (const float*)d_in[0];
    const float* s_inputs = (const float*)d_in[1];
    const float* ln_gamma = (const float*)d_in[2];
    const float* ln_beta  = (const float*)d_in[3];
    const float* Wq1 = (const float*)d_in[4];
    const float* Wq2 = (const float*)d_in[5];
    const float* Wq3 = (const float*)d_in[6];
    const float* Wk1 = (const float*)d_in[7];
    const float* Wk2 = (const float*)d_in[8];
    const float* Wk3 = (const float*)d_in[9];
    const float* Wq_att = (const float*)d_in[10];
    const float* Wk_att = (const float*)d_in[11];
    const float* Wv_att = (const float*)d_in[12];
    const float* Wg  = (const float*)d_in[13];
    const float* bg  = (const float*)d_in[14];
    const float* Wo  = (const float*)d_in[15];
    const float* bo  = (const float*)d_in[16];
    float* out = (float*)d_out;

    const int SMEM_PROJ = 64 * 128 * 4 + 2 * 128 * 128 * 4;  // 163840
    const int SMEM_ATTN = 2 * NN * DH * 4;                    // 98304
    const int SMEM_OUT  = 64 * 128 * 4 + 128 * 128 * 4;       // 98304
    const int SMEM_BIAS = 2 * 64 * 97 * 4;                    // 49664
    cudaFuncSetAttribute(k_proj, cudaFuncAttributeMaxDynamicSharedMemorySize, SMEM_PROJ);
    cudaFuncSetAttribute(k_attn, cudaFuncAttributeMaxDynamicSharedMemorySize, SMEM_ATTN);
    cudaFuncSetAttribute(k_out,  cudaFuncAttributeMaxDynamicSharedMemorySize, SMEM_OUT);
    cudaFuncSetAttribute(k_biasmat, cudaFuncAttributeMaxDynamicSharedMemorySize, SMEM_BIAS);

    k_ln<<<MROWS / 8, 256>>>(x, ln_gamma, ln_beta);
    k_mean<<<dim3(NN, 2), 128>>>();
    k_mlp<<<dim3(NN / 8, 2), 256>>>(s_inputs, Wq1, Wq2, Wq3, Wk1, Wk2, Wk3);
    k_biasmat<<<dim3(NN / 64, NN / 64, NH), 256, SMEM_BIAS>>>();
    k_proj<<<MROWS / 64, 256, SMEM_PROJ>>>(Wq_att, Wk_att, Wv_att, Wg, bg);
    k_attn<<<dim3(NN, NH), 192, SMEM_ATTN>>>();
    k_out<<<MROWS / 64, 256, SMEM_OUT>>>(Wo, bo, out);
}

// round 13
// speedup vs baseline: 1.0170x; 1.0170x over previous
#include <cuda_runtime.h>
#include <math.h>

#define NN 384
#define C 128
#define NH 4
#define DH 32
#define HD 128
#define RK 96
#define SD 449
#define ZD 577
#define MH 256
#define MROWS (NN * NN)

typedef unsigned long long ull;

// ---- scratch (device globals; no allocation) ----
__device__ float g_xln[MROWS * C];
__device__ float g_q[MROWS * HD];
__device__ float g_k[MROWS * HD];
__device__ float g_v[MROWS * HD];
__device__ float g_gt[MROWS * HD];
__device__ float g_o[MROWS * HD];
__device__ float g_mean[2 * NN * C];
__device__ float g_qb[NH * NN * RK];
__device__ float g_kb[NH * NN * RK];
__device__ float g_bias[NH * NN * NN];

// ---- f32x2 packed helpers (FFMA2 path, sm_103a) ----
__device__ __forceinline__ ull d2(float v) {
    ull r; asm("mov.b64 %0, {%1, %1};" : "=l"(r) : "f"(v)); return r;
}
__device__ __forceinline__ void fma2(ull& d, ull a, ull b) {
    asm("fma.rn.f32x2 %0, %1, %2, %0;" : "+l"(d) : "l"(a), "l"(b));
}
__device__ __forceinline__ ull add2(ull a, ull b) {
    ull r; asm("add.rn.f32x2 %0, %1, %2;" : "=l"(r) : "l"(a), "l"(b)); return r;
}
__device__ __forceinline__ ull mul2(ull a, ull b) {
    ull r; asm("mul.rn.f32x2 %0, %1, %2;" : "=l"(r) : "l"(a), "l"(b)); return r;
}
__device__ __forceinline__ float2 unpk(ull v) {
    float2 f; asm("mov.b64 {%0, %1}, %2;" : "=f"(f.x), "=f"(f.y) : "l"(v)); return f;
}

// ---------------- LayerNorm: one warp per 128-ch row ----------------
__global__ __launch_bounds__(256) void k_ln(const float* __restrict__ x,
                                            const float* __restrict__ gamma,
                                            const float* __restrict__ beta) {
    int row = blockIdx.x * 8 + (threadIdx.x >> 5);
    int lane = threadIdx.x & 31;
    float4 v = reinterpret_cast<const float4*>(x + (size_t)row * C)[lane];
    float s = v.x + v.y + v.z + v.w;
    float s2 = v.x * v.x + v.y * v.y + v.z * v.z + v.w * v.w;
#pragma unroll
    for (int o = 16; o; o >>= 1) {
        s += __shfl_xor_sync(0xffffffffu, s, o);
        s2 += __shfl_xor_sync(0xffffffffu, s2, o);
    }
    float mu = s * (1.0f / C);
    float var = fmaxf(s2 * (1.0f / C) - mu * mu, 0.0f);
    float rs = rsqrtf(var + 1e-5f);
    float4 g4 = reinterpret_cast<const float4*>(gamma)[lane];
    float4 b4 = reinterpret_cast<const float4*>(beta)[lane];
    float4 o4;
    o4.x = (v.x - mu) * rs * g4.x + b4.x;
    o4.y = (v.y - mu) * rs * g4.y + b4.y;
    o4.z = (v.z - mu) * rs * g4.z + b4.z;
    o4.w = (v.w - mu) * rs * g4.w + b4.w;
    reinterpret_cast<float4*>(g_xln + (size_t)row * C)[lane] = o4;
}

// ---------------- row/col means ----------------
__global__ __launch_bounds__(128) void k_mean() {
    int n = blockIdx.x, c = threadIdx.x;
    float s = 0.f;
    if (blockIdx.y == 0) {
        const float* p = g_xln + (size_t)n * NN * C + c;
#pragma unroll 4
        for (int j = 0; j < NN; ++j) s += p[(size_t)j * C];
    } else {
        const float* p = g_xln + (size_t)n * C + c;
#pragma unroll 4
        for (int i = 0; i < NN; ++i) s += p[(size_t)i * NN * C];
    }
    g_mean[blockIdx.y * NN * C + n * C + c] = s * (1.0f / NN);
}

// ---------------- bias MLPs, 8 sequence positions per block ----------------
__global__ __launch_bounds__(256) void k_mlp(const float* __restrict__ s_inputs,
                                             const float* __restrict__ Wq1, const float* __restrict__ Wq2,
                                             const float* __restrict__ Wq3, const float* __restrict__ Wk1,
                                             const float* __restrict__ Wk2, const float* __restrict__ Wk3) {
    __shared__ float z[8][ZD];
    __shared__ float h1[8][MH];
    __shared__ float h2[8][MH];
    int n0 = blockIdx.x * 8, t = threadIdx.x;
    int which = blockIdx.y;
    const float* mean = g_mean + which * NN * C;
    const float* W1 = which ? Wk1 : Wq1;
    const float* W2 = which ? Wk2 : Wq2;
    const float* W3 = which ? Wk3 : Wq3;
    float* outb = which ? g_kb : g_qb;

    for (int idx = t; idx < 8 * ZD; idx += 256) {
        int n = idx / ZD, c = idx - n * ZD;
        z[n][c] = (c < C) ? mean[(n0 + n) * C + c] : s_inputs[(n0 + n) * SD + (c - C)];
    }
    __syncthreads();
    {
        float a[8];
#pragma unroll
        for (int n = 0; n < 8; ++n) a[n] = 0.f;
        for (int k = 0; k < ZD; ++k) {
            float wv = W1[k * MH + t];
#pragma unroll
            for (int n = 0; n < 8; ++n) a[n] = fmaf(z[n][k], wv, a[n]);
        }
#pragma unroll
        for (int n = 0; n < 8; ++n) h1[n][t] = tanhf(a[n]);
    }
    __syncthreads();
    {
        float a[8];
#pragma unroll
        for (int n = 0; n < 8; ++n) a[n] = 0.f;
        for (int k = 0; k < MH; ++k) {
            float wv = W2[k * MH + t];
#pragma unroll
            for (int n = 0; n < 8; ++n) a[n] = fmaf(h1[n][k], wv, a[n]);
        }
#pragma unroll
        for (int n = 0; n < 8; ++n) h2[n][t] = tanhf(a[n]);
    }
    __syncthreads();
    for (int o = t; o < NH * RK; o += 256) {
        float b[8];
#pragma unroll
        for (int n = 0; n < 8; ++n) b[n] = 0.f;
        for (int k = 0; k < MH; ++k) {
            float wv = W3[k * (NH * RK) + o];
#pragma unroll
            for (int n = 0; n < 8; ++n) b[n] = fmaf(h2[n][k], wv, b[n]);
        }
        int hh = o / RK, r = o - hh * RK;
#pragma unroll
        for (int n = 0; n < 8; ++n) outb[(hh * NN + n0 + n) * RK + r] = b[n];
    }
}

// ---------------- low-rank bias matrix: tiled B[h] = qb @ kb^T ----------------
__global__ __launch_bounds__(256) void k_biasmat() {
    extern __shared__ float smb[];
    float* qs = smb;             // [64][97]
    float* ks = smb + 64 * 97;   // [64][97]
    int q0 = blockIdx.x * 64, k0 = blockIdx.y * 64, h = blockIdx.z;
    for (int idx = threadIdx.x; idx < 64 * RK; idx += 256) {
        int row = idx / RK, r = idx - row * RK;
        qs[row * 97 + r] = g_qb[(h * NN + q0 + row) * RK + r];
        ks[row * 97 + r] = g_kb[(h * NN + k0 + row) * RK + r];
    }
    __syncthreads();
    int tx = threadIdx.x & 15, ty = threadIdx.x >> 4;
    float acc[4][4];
#pragma unroll
    for (int i = 0; i < 4; ++i)
#pragma unroll
        for (int j = 0; j < 4; ++j) acc[i][j] = 0.f;
    for (int r = 0; r < RK; ++r) {
        float qv[4], kv[4];
#pragma unroll
        for (int i = 0; i < 4; ++i) qv[i] = qs[(ty * 4 + i) * 97 + r];
#pragma unroll
        for (int j = 0; j < 4; ++j) kv[j] = ks[(tx * 4 + j) * 97 + r];
#pragma unroll
        for (int i = 0; i < 4; ++i)
#pragma unroll
            for (int j = 0; j < 4; ++j) acc[i][j] = fmaf(qv[i], kv[j], acc[i][j]);
    }
#pragma unroll
    for (int i = 0; i < 4; ++i) {
        float4 o4 = {acc[i][0], acc[i][1], acc[i][2], acc[i][3]};
        *reinterpret_cast<float4*>(g_bias + ((size_t)(h * NN + q0 + ty * 4 + i)) * NN + k0 + tx * 4) = o4;
    }
}

// ---------------- fused QKVG projection GEMM (f32x2, 2 weights resident) ----------------
__global__ __launch_bounds__(256) void k_proj(const float* __restrict__ Wq, const float* __restrict__ Wk,
                                              const float* __restrict__ Wv, const float* __restrict__ Wg,
                                              const float* __restrict__ bg) {
    extern __shared__ float sm[];
    float* Xs = sm;                 // [64][128]
    float* Ws0 = sm + 64 * 128;     // [128][128]
    float* Ws1 = Ws0 + 128 * 128;   // [128][128]
    int row0 = blockIdx.x * 64;
    {
        const float4* src = reinterpret_cast<const float4*>(g_xln + (size_t)row0 * C);
        float4* d4 = reinterpret_cast<float4*>(Xs);
        for (int idx = threadIdx.x; idx < 64 * 128 / 4; idx += 256) d4[idx] = src[idx];
    }
    int tx = threadIdx.x & 31, ty = threadIdx.x >> 5;
    const float* WA[4] = {Wq, Wk, Wv, Wg};
    float* OA[4] = {g_q, g_k, g_v, g_gt};
    float4 bg4 = reinterpret_cast<const float4*>(bg)[tx];

#pragma unroll 1
    for (int pass = 0; pass < 2; ++pass) {
        __syncthreads();
        {
            const float4* s0 = reinterpret_cast<const float4*>(WA[2 * pass]);
            const float4* s1 = reinterpret_cast<const float4*>(WA[2 * pass + 1]);
            float4* d0 = reinterpret_cast<float4*>(Ws0);
            float4* d1 = reinterpret_cast<float4*>(Ws1);
            for (int idx = threadIdx.x; idx < 128 * 128 / 4; idx += 256) {
                d0[idx] = s0[idx];
                d1[idx] = s1[idx];
            }
        }
        __syncthreads();
        ull acc[8][2][2];
#pragma unroll
        for (int i = 0; i < 8; ++i)
#pragma unroll
            for (int w = 0; w < 2; ++w) { acc[i][w][0] = 0ull; acc[i][w][1] = 0ull; }

        for (int k0 = 0; k0 < 128; k0 += 4) {
            ulonglong2 w0[4], w1[4];
#pragma unroll
            for (int j = 0; j < 4; ++j) {
                w0[j] = reinterpret_cast<const ulonglong2*>(Ws0 + (k0 + j) * 128)[tx];
                w1[j] = reinterpret_cast<const ulonglong2*>(Ws1 + (k0 + j) * 128)[tx];
            }
#pragma unroll
            for (int i = 0; i < 8; ++i) {
                float4 xv = *reinterpret_cast<const float4*>(Xs + (ty + 8 * i) * 128 + k0);
                ull xd[4] = {d2(xv.x), d2(xv.y), d2(xv.z), d2(xv.w)};
#pragma unroll
                for (int j = 0; j < 4; ++j) {
                    fma2(acc[i][0][0], xd[j], w0[j].x);
                    fma2(acc[i][0][1], xd[j], w0[j].y);
                    fma2(acc[i][1][0], xd[j], w1[j].x);
                    fma2(acc[i][1][1], xd[j], w1[j].y);
                }
            }
        }
#pragma unroll
        for (int w = 0; w < 2; ++w) {
            int wi = 2 * pass + w;
            float* outp = OA[wi];
#pragma unroll
            for (int i = 0; i < 8; ++i) {
                float2 a = unpk(acc[i][w][0]), b = unpk(acc[i][w][1]);
                float vals[4] = {a.x, a.y, b.x, b.y};
                float bb[4] = {bg4.x, bg4.y, bg4.z, bg4.w};
#pragma unroll
                for (int c = 0; c < 4; ++c) {
                    if (wi == 0) vals[c] *= 0.17677669529663687f;  // 1/sqrt(32)
                    if (wi == 3) vals[c] = 1.0f / (1.0f + __expf(-(vals[c] + bb[c])));
                }
                float4 o4 = {vals[0], vals[1], vals[2], vals[3]};
                *reinterpret_cast<float4*>(outp + (size_t)(row0 + ty + 8 * i) * 128 + tx * 4) = o4;
            }
        }
    }
}

// ---------------- attention: block per (row i, head h), 2 q-rows per thread ----------------
__global__ __launch_bounds__(192, 1) void k_attn() {
    extern __shared__ float sm[];
    float* Ks = sm;              // [384][32]
    float* Vs = sm + NN * DH;    // [384][32]
    int i = blockIdx.x, h = blockIdx.y;
    int tid = threadIdx.x;
    size_t base = ((size_t)i * NN) * HD + h * DH;

    for (int idx = tid; idx < NN * DH / 4; idx += 192) {
        int k = idx >> 3, d4 = idx & 7;
        reinterpret_cast<float4*>(Ks)[idx] = *reinterpret_cast<const float4*>(g_k + base + (size_t)k * HD + d4 * 4);
        reinterpret_cast<float4*>(Vs)[idx] = *reinterpret_cast<const float4*>(g_v + base + (size_t)k * HD + d4 * 4);
    }
    __syncthreads();

    int qA = tid, qB = tid + 192;
    ull qa[16], qb[16];
    {
        const ulonglong2* pa = reinterpret_cast<const ulonglong2*>(g_q + base + (size_t)qA * HD);
        const ulonglong2* pb = reinterpret_cast<const ulonglong2*>(g_q + base + (size_t)qB * HD);
#pragma unroll
        for (int t = 0; t < 8; ++t) {
            ulonglong2 ua = pa[t], ub = pb[t];
            qa[2 * t] = ua.x; qa[2 * t + 1] = ua.y;
            qb[2 * t] = ub.x; qb[2 * t + 1] = ub.y;
        }
    }
    const float4* browA = reinterpret_cast<const float4*>(g_bias + ((size_t)(h * NN + qA)) * NN);
    const float4* browB = reinterpret_cast<const float4*>(g_bias + ((size_t)(h * NN + qB)) * NN);

    float ma = -INFINITY, la = 0.f, mb = -INFINITY, lb = 0.f;
    ull aa[16], ab[16];
#pragma unroll
    for (int t = 0; t < 16; ++t) { aa[t] = 0ull; ab[t] = 0ull; }

    float4 pba = browA[0], pbb = browB[0];

    for (int k0 = 0; k0 < NN; k0 += 4) {
        float4 b4a = pba, b4b = pbb;
        if (k0 + 4 < NN) { pba = browA[(k0 >> 2) + 1]; pbb = browB[(k0 >> 2) + 1]; }
        float sva[4] = {b4a.x, b4a.y, b4a.z, b4a.w};
        float svb[4] = {b4b.x, b4b.y, b4b.z, b4b.w};
#pragma unroll
        for (int j = 0; j < 4; ++j) {
            const ulonglong2* kp = reinterpret_cast<const ulonglong2*>(Ks + (k0 + j) * DH);
            ull sA0 = 0ull, sB0 = 0ull, sA1 = 0ull, sB1 = 0ull;
#pragma unroll
            for (int t = 0; t < 8; ++t) {
                ulonglong2 kk = kp[t];
                fma2(sA0, qa[2 * t], kk.x);
                fma2(sB0, qa[2 * t + 1], kk.y);
                fma2(sA1, qb[2 * t], kk.x);
                fma2(sB1, qb[2 * t + 1], kk.y);
            }
            float2 r0 = unpk(add2(sA0, sB0));
            float2 r1 = unpk(add2(sA1, sB1));
            sva[j] += r0.x + r0.y;
            svb[j] += r1.x + r1.y;
        }
        // online softmax for qA
        float mxa = fmaxf(fmaxf(sva[0], sva[1]), fmaxf(sva[2], sva[3]));
        if (mxa > ma) {
            float sc = __expf(ma - mxa);
            ull sc2 = d2(sc);
#pragma unroll
            for (int t = 0; t < 16; ++t) aa[t] = mul2(aa[t], sc2);
            la *= sc;
            ma = mxa;
        }
        float mxb = fmaxf(fmaxf(svb[0], svb[1]), fmaxf(svb[2], svb[3]));
        if (mxb > mb) {
            float sc = __expf(mb - mxb);
            ull sc2 = d2(sc);
#pragma unroll
            for (int t = 0; t < 16; ++t) ab[t] = mul2(ab[t], sc2);
            lb *= sc;
            mb = mxb;
        }
        float pa4[4], pb4[4];
#pragma unroll
        for (int j = 0; j < 4; ++j) {
            pa4[j] = __expf(sva[j] - ma);
            pb4[j] = __expf(svb[j] - mb);
        }
        la += pa4[0] + pa4[1] + pa4[2] + pa4[3];
        lb += pb4[0] + pb4[1] + pb4[2] + pb4[3];
#pragma unroll
        for (int j = 0; j < 4; ++j) {
            ull p2a = d2(pa4[j]);
            ull p2b = d2(pb4[j]);
            const ulonglong2* vp = reinterpret_cast<const ulonglong2*>(Vs + (k0 + j) * DH);
#pragma unroll
            for (int t = 0; t < 8; ++t) {
                ulonglong2 vv = vp[t];
                fma2(aa[2 * t], p2a, vv.x);
                fma2(aa[2 * t + 1], p2a, vv.y);
                fma2(ab[2 * t], p2b, vv.x);
                fma2(ab[2 * t + 1], p2b, vv.y);
            }
        }
    }
    float ia = 1.0f / la, ib = 1.0f / lb;
    float* opa = g_o + base + (size_t)qA * HD;
    float* opb = g_o + base + (size_t)qB * HD;
#pragma unroll
    for (int t = 0; t < 8; ++t) {
        float2 a0 = unpk(aa[2 * t]), a1 = unpk(aa[2 * t + 1]);
        float2 b0 = unpk(ab[2 * t]), b1 = unpk(ab[2 * t + 1]);
        float4 o4a = {a0.x * ia, a0.y * ia, a1.x * ia, a1.y * ia};
        float4 o4b = {b0.x * ib, b0.y * ib, b1.x * ib, b1.y * ib};
        *reinterpret_cast<float4*>(opa + t * 4) = o4a;
        *reinterpret_cast<float4*>(opb + t * 4) = o4b;
    }
}

// ---------------- output: (g*o) @ Wo + bo (f32x2) ----------------
__global__ __launch_bounds__(256) void k_out(const float* __restrict__ Wo, const float* __restrict__ bo,
                                             float* __restrict__ out) {
    extern __shared__ float sm[];
    float* Xs = sm;
    float* Ws = sm + 64 * 128;
    int row0 = blockIdx.x * 64;
    {
        const float4* sg = reinterpret_cast<const float4*>(g_gt + (size_t)row0 * 128);
        const float4* so = reinterpret_cast<const float4*>(g_o + (size_t)row0 * 128);
        float4* d4 = reinterpret_cast<float4*>(Xs);
        for (int idx = threadIdx.x; idx < 64 * 128 / 4; idx += 256) {
            float4 a = sg[idx], b = so[idx];
            d4[idx] = make_float4(a.x * b.x, a.y * b.y, a.z * b.z, a.w * b.w);
        }
        const float4* src = reinterpret_cast<const float4*>(Wo);
        float4* w4 = reinterpret_cast<float4*>(Ws);
        for (int idx = threadIdx.x; idx < 128 * 128 / 4; idx += 256) w4[idx] = src[idx];
    }
    __syncthreads();
    int tx = threadIdx.x & 31, ty = threadIdx.x >> 5;
    ull acc[8][2];
#pragma unroll
    for (int i = 0; i < 8; ++i) { acc[i][0] = 0ull; acc[i][1] = 0ull; }

    for (int k0 = 0; k0 < 128; k0 += 4) {
        ulonglong2 wv[4];
#pragma unroll
        for (int j = 0; j < 4; ++j)
            wv[j] = reinterpret_cast<const ulonglong2*>(Ws + (k0 + j) * 128)[tx];
#pragma unroll
        for (int i = 0; i < 8; ++i) {
            float4 xv = *reinterpret_cast<const float4*>(Xs + (ty + 8 * i) * 128 + k0);
            ull xd[4] = {d2(xv.x), d2(xv.y), d2(xv.z), d2(xv.w)};
#pragma unroll
            for (int j = 0; j < 4; ++j) {
                fma2(acc[i][0], xd[j], wv[j].x);
                fma2(acc[i][1], xd[j], wv[j].y);
            }
        }
    }
    float4 bo4 = reinterpret_cast<const float4*>(bo)[tx];
#pragma unroll
    for (int i = 0; i < 8; ++i) {
        float2 a = unpk(acc[i][0]), b = unpk(acc[i][1]);
        float4 o4 = {a.x + bo4.x, a.y + bo4.y, b.x + bo4.z, b.y + bo4.w};
        *reinterpret_cast<float4*>(out + (size_t)(row0 + ty + 8 * i) * 128 + tx * 4) = o4;
    }
}

extern "C" void kernel_launch(void* const* d_in, const int* in_sizes, int n_in,
                              void* d_out, int out_size) {
    const float* x        = (const float*)d_in[0];
    const float* s_inputs = (const float*)d_in[1];
    const float* ln_gamma = (const float*)d_in[2];
    const float* ln_beta  = (const float*)d_in[3];
    const float* Wq1 = (const float*)d_in[4];
    const float* Wq2 = (const float*)d_in[5];
    const float* Wq3 = (const float*)d_in[6];
    const float* Wk1 = (const float*)d_in[7];
    const float* Wk2 = (const float*)d_in[8];
    const float* Wk3 = (const float*)d_in[9];
    const float* Wq_att = (const float*)d_in[10];
    const float* Wk_att = (const float*)d_in[11];
    const float* Wv_att = (const float*)d_in[12];
    const float* Wg  = (const float*)d_in[13];
    const float* bg  = (const float*)d_in[14];
    const float* Wo  = (const float*)d_in[15];
    const float* bo  = (const float*)d_in[16];
    float* out = (float*)d_out;

    const int SMEM_PROJ = 64 * 128 * 4 + 2 * 128 * 128 * 4;  // 163840
    const int SMEM_ATTN = 2 * NN * DH * 4;                    // 98304
    const int SMEM_OUT  = 64 * 128 * 4 + 128 * 128 * 4;       // 98304
    const int SMEM_BIAS = 2 * 64 * 97 * 4;                    // 49664
    cudaFuncSetAttribute(k_proj, cudaFuncAttributeMaxDynamicSharedMemorySize, SMEM_PROJ);
    cudaFuncSetAttribute(k_attn, cudaFuncAttributeMaxDynamicSharedMemorySize, SMEM_ATTN);
    cudaFuncSetAttribute(k_out,  cudaFuncAttributeMaxDynamicSharedMemorySize, SMEM_OUT);
    cudaFuncSetAttribute(k_biasmat, cudaFuncAttributeMaxDynamicSharedMemorySize, SMEM_BIAS);

    k_ln<<<MROWS / 8, 256>>>(x, ln_gamma, ln_beta);
    k_mean<<<dim3(NN, 2), 128>>>();
    k_mlp<<<dim3(NN / 8, 2), 256>>>(s_inputs, Wq1, Wq2, Wq3, Wk1, Wk2, Wk3);
    k_biasmat<<<dim3(NN / 64, NN / 64, NH), 256, SMEM_BIAS>>>();
    k_proj<<<MROWS / 64, 256, SMEM_PROJ>>>(Wq_att, Wk_att, Wv_att, Wg, bg);
    k_attn<<<dim3(NN, NH), 192, SMEM_ATTN>>>();
    k_out<<<MROWS / 64, 256, SMEM_OUT>>>(Wo, bo, out);
}